// round 6
// baseline (speedup 1.0000x reference)
#include <cuda_runtime.h>
#include <cuda_bf16.h>

// Problem constants: N=50000 nodes, D=256, HS=32, E=1.6M edges
#define MAXN 50048
#define MAXE 1600000

__device__ float g_Q[MAXN * 32];
__device__ float g_K[MAXN * 32];
__device__ float g_V[MAXN * 32];
__device__ int   g_cnt[MAXN];
__device__ int   g_off[MAXN + 1];
__device__ int   g_cur[MAXN];
__device__ int   g_sorted[MAXE];
__device__ int   g_bsum[64];
__device__ int   g_bbase[64];

// ---------------------------------------------------------------------------
__global__ void zero_cnt_kernel(int n) {
    int i = blockIdx.x * blockDim.x + threadIdx.x;
    if (i < n) g_cnt[i] = 0;
}

// ---------------------------------------------------------------------------
// QKV projection: 128 thr, tile 128x96, packed f32x2 FMAs. (at fp32 floor)
// ---------------------------------------------------------------------------
#define QKV_TM 128

__global__ __launch_bounds__(128) void qkv_kernel(
    const float* __restrict__ X,
    const float* __restrict__ Wq,
    const float* __restrict__ Wk,
    const float* __restrict__ Wv,
    int nNodes)
{
    __shared__ float Xs[32][QKV_TM + 4];
    __shared__ float Ws[32][96];

    const int tid = threadIdx.x;
    const int tx  = tid & 15;
    const int ty  = tid >> 4;
    const int m0  = blockIdx.x * QKV_TM;

    unsigned long long accp[8][6];
    #pragma unroll
    for (int i = 0; i < 8; ++i)
        #pragma unroll
        for (int j = 0; j < 6; ++j) accp[i][j] = 0ull;

    for (int kc = 0; kc < 256; kc += 32) {
        #pragma unroll
        for (int it = 0; it < 8; ++it) {
            int idx = it * 128 + tid;
            int row = idx >> 3;
            int kq  = idx & 7;
            int gm  = m0 + row;
            float4 v = make_float4(0.f, 0.f, 0.f, 0.f);
            if (gm < nNodes)
                v = *reinterpret_cast<const float4*>(&X[gm * 256 + kc + kq * 4]);
            int kk = kq * 4;
            Xs[kk + 0][row] = v.x;
            Xs[kk + 1][row] = v.y;
            Xs[kk + 2][row] = v.z;
            Xs[kk + 3][row] = v.w;
        }
        #pragma unroll
        for (int idx = tid; idx < 32 * 96; idx += 128) {
            int k = idx / 96, j = idx - k * 96;
            const float* Wp = (j < 32) ? Wq : ((j < 64) ? Wk : Wv);
            Ws[k][j] = Wp[(kc + k) * 32 + (j & 31)];
        }
        __syncthreads();

        #pragma unroll
        for (int k = 0; k < 32; ++k) {
            float4 a0 = *reinterpret_cast<const float4*>(&Xs[k][tx * 4]);
            float4 a1 = *reinterpret_cast<const float4*>(&Xs[k][64 + tx * 4]);
            ulonglong2 b01 = *reinterpret_cast<const ulonglong2*>(&Ws[k][ty * 12]);
            ulonglong2 b23 = *reinterpret_cast<const ulonglong2*>(&Ws[k][ty * 12 + 4]);
            ulonglong2 b45 = *reinterpret_cast<const ulonglong2*>(&Ws[k][ty * 12 + 8]);
            unsigned long long bb[6] = {b01.x, b01.y, b23.x, b23.y, b45.x, b45.y};
            float av[8] = {a0.x, a0.y, a0.z, a0.w, a1.x, a1.y, a1.z, a1.w};
            #pragma unroll
            for (int i = 0; i < 8; ++i) {
                unsigned long long ad;
                asm("mov.b64 %0, {%1, %1};" : "=l"(ad) : "f"(av[i]));
                #pragma unroll
                for (int j = 0; j < 6; ++j)
                    asm("fma.rn.f32x2 %0, %1, %2, %0;"
                        : "+l"(accp[i][j]) : "l"(ad), "l"(bb[j]));
            }
        }
        __syncthreads();
    }

    const float qscale = 0.17677669529663687f;
    #pragma unroll
    for (int i = 0; i < 8; ++i) {
        int node = m0 + ((i < 4) ? (tx * 4 + i) : (64 + tx * 4 + i - 4));
        if (node >= nNodes) continue;
        #pragma unroll
        for (int j2 = 0; j2 < 6; ++j2) {
            float2 p = *reinterpret_cast<float2*>(&accp[i][j2]);
            int jj = ty * 12 + j2 * 2;
            float* dst = (jj < 32) ? g_Q : ((jj < 64) ? g_K : g_V);
            if (jj < 32) { p.x *= qscale; p.y *= qscale; }
            dst[node * 32 + (jj & 31)]     = p.x;
            dst[node * 32 + (jj & 31) + 1] = p.y;
        }
    }
}

// ---------------------------------------------------------------------------
__global__ void hist_kernel(const int* __restrict__ ei, int nEdges) {
    int i = blockIdx.x * blockDim.x + threadIdx.x;
    int e4 = i * 4;
    if (e4 + 3 < nEdges) {
        int4 r = *reinterpret_cast<const int4*>(&ei[e4]);
        atomicAdd(&g_cnt[r.x], 1);
        atomicAdd(&g_cnt[r.y], 1);
        atomicAdd(&g_cnt[r.z], 1);
        atomicAdd(&g_cnt[r.w], 1);
    } else {
        for (int e = e4; e < nEdges; ++e) atomicAdd(&g_cnt[ei[e]], 1);
    }
}

__global__ __launch_bounds__(1024) void scan_sum_kernel(int n) {
    int i = blockIdx.x * 1024 + threadIdx.x;
    int v = (i < n) ? g_cnt[i] : 0;
    #pragma unroll
    for (int o = 16; o; o >>= 1) v += __shfl_xor_sync(~0u, v, o);
    __shared__ int ws[32];
    if ((threadIdx.x & 31) == 0) ws[threadIdx.x >> 5] = v;
    __syncthreads();
    if (threadIdx.x < 32) {
        int s = ws[threadIdx.x];
        #pragma unroll
        for (int o = 16; o; o >>= 1) s += __shfl_xor_sync(~0u, s, o);
        if (threadIdx.x == 0) g_bsum[blockIdx.x] = s;
    }
}

__global__ void scan_base_kernel(int nb, int n) {
    __shared__ int sh[64];
    int t = threadIdx.x;
    int v = (t < nb) ? g_bsum[t] : 0;
    sh[t] = v;
    __syncthreads();
    #pragma unroll
    for (int o = 1; o < 64; o <<= 1) {
        int x = (t >= o) ? sh[t - o] : 0;
        __syncthreads();
        sh[t] += x;
        __syncthreads();
    }
    if (t < nb) g_bbase[t] = sh[t] - v;
    if (t == 63) g_off[n] = sh[63];
}

__global__ __launch_bounds__(1024) void scan_write_kernel(int n) {
    int i = blockIdx.x * 1024 + threadIdx.x;
    int lane = threadIdx.x & 31, w = threadIdx.x >> 5;
    int v = (i < n) ? g_cnt[i] : 0;
    int x = v;
    #pragma unroll
    for (int o = 1; o < 32; o <<= 1) {
        int y = __shfl_up_sync(~0u, x, o);
        if (lane >= o) x += y;
    }
    __shared__ int ws[32];
    if (lane == 31) ws[w] = x;
    __syncthreads();
    if (w == 0) {
        int s = ws[lane];
        #pragma unroll
        for (int o = 1; o < 32; o <<= 1) {
            int y = __shfl_up_sync(~0u, s, o);
            if (lane >= o) s += y;
        }
        ws[lane] = s;
    }
    __syncthreads();
    int base = g_bbase[blockIdx.x] + (w ? ws[w - 1] : 0);
    if (i < n) {
        int excl = base + x - v;
        g_off[i] = excl;
        g_cur[i] = excl;
    }
}

__global__ void scatter_kernel(const int* __restrict__ ei, int nEdges) {
    int i = blockIdx.x * blockDim.x + threadIdx.x;
    int e4 = i * 4;
    if (e4 + 3 < nEdges) {
        int4 r = *reinterpret_cast<const int4*>(&ei[e4]);
        int4 c = *reinterpret_cast<const int4*>(&ei[nEdges + e4]);
        g_sorted[atomicAdd(&g_cur[r.x], 1)] = c.x;
        g_sorted[atomicAdd(&g_cur[r.y], 1)] = c.y;
        g_sorted[atomicAdd(&g_cur[r.z], 1)] = c.z;
        g_sorted[atomicAdd(&g_cur[r.w], 1)] = c.w;
    } else {
        for (int e = e4; e < nEdges; ++e)
            g_sorted[atomicAdd(&g_cur[ei[e]], 1)] = ei[nEdges + e];
    }
}

// ---------------------------------------------------------------------------
// Attention. One warp per node. Lane layout: g=lane>>3 (row in quad),
// c4=lane&7 (4-col group). Fully in-lane per tile: after the 3-level
// butterfly every lane of a row group holds the score, so exp + V-FMA need
// no smem/shfl redistribution. Denominator deferred to one final reduce.
// ---------------------------------------------------------------------------
__global__ __launch_bounds__(256) void attn_kernel(float* __restrict__ out, int nNodes) {
    __shared__ float osh[8][32];

    const int wIn  = threadIdx.x >> 5;
    const int lane = threadIdx.x & 31;
    const int node = blockIdx.x * 8 + wIn;
    if (node >= nNodes) return;

    const int s = g_off[node];
    const int e = g_off[node + 1];

    const int c4 = lane & 7;
    const int g  = lane >> 3;

    float q = g_Q[node * 32 + lane];  // pre-scaled by 1/sqrt(32)
    float qc0 = __shfl_sync(~0u, q, c4 * 4 + 0);
    float qc1 = __shfl_sync(~0u, q, c4 * 4 + 1);
    float qc2 = __shfl_sync(~0u, q, c4 * 4 + 2);
    float qc3 = __shfl_sync(~0u, q, c4 * 4 + 3);

    float dsum = 0.f;                                // 8x over-counted denom
    unsigned long long accp0 = 0ull, accp1 = 0ull;   // cols c4*4..+3 partials

    for (int base = s; base < e; base += 32) {
        const int n = min(32, e - base);
        int cb = (base + lane < e) ? g_sorted[base + lane] : 0;

        // gather K/V fragments: up to 16 independent LDG.128, tail-predicated
        float4 kr[8], vr[8];
        #pragma unroll
        for (int it = 0; it < 8; ++it) {
            int row = it * 4 + g;
            int c = __shfl_sync(~0u, cb, row);
            c = (row < n) ? c : 0;   // safe address even when predicated off
            if (row < n) {
                kr[it] = *reinterpret_cast<const float4*>(&g_K[c * 32 + c4 * 4]);
                vr[it] = *reinterpret_cast<const float4*>(&g_V[c * 32 + c4 * 4]);
            } else {
                kr[it] = make_float4(0.f, 0.f, 0.f, 0.f);
                vr[it] = make_float4(0.f, 0.f, 0.f, 0.f);
            }
        }

        // per row group: dot4 -> butterfly over c4 -> in-lane exp -> V FMA
        #pragma unroll
        for (int it = 0; it < 8; ++it) {
            int row = it * 4 + g;
            float p = qc0 * kr[it].x;
            p = fmaf(qc1, kr[it].y, p);
            p = fmaf(qc2, kr[it].z, p);
            p = fmaf(qc3, kr[it].w, p);
            p += __shfl_xor_sync(~0u, p, 1);
            p += __shfl_xor_sync(~0u, p, 2);
            p += __shfl_xor_sync(~0u, p, 4);
            float ex = (row < n) ? __expf(p) : 0.f;
            dsum += ex;
            unsigned long long wd;
            asm("mov.b64 %0, {%1, %1};" : "=l"(wd) : "f"(ex));
            unsigned long long v01 = *reinterpret_cast<unsigned long long*>(&vr[it].x);
            unsigned long long v23 = *reinterpret_cast<unsigned long long*>(&vr[it].z);
            asm("fma.rn.f32x2 %0, %1, %2, %0;" : "+l"(accp0) : "l"(wd), "l"(v01));
            asm("fma.rn.f32x2 %0, %1, %2, %0;" : "+l"(accp1) : "l"(wd), "l"(v23));
        }
    }

    // final reductions: columns over g bits; denom over all lanes (/8)
    float a0 = reinterpret_cast<float2*>(&accp0)->x;
    float a1 = reinterpret_cast<float2*>(&accp0)->y;
    float a2 = reinterpret_cast<float2*>(&accp1)->x;
    float a3 = reinterpret_cast<float2*>(&accp1)->y;
    #pragma unroll
    for (int m = 8; m <= 16; m <<= 1) {
        a0 += __shfl_xor_sync(~0u, a0, m);
        a1 += __shfl_xor_sync(~0u, a1, m);
        a2 += __shfl_xor_sync(~0u, a2, m);
        a3 += __shfl_xor_sync(~0u, a3, m);
    }
    float t = dsum;
    t += __shfl_xor_sync(~0u, t, 16);
    t += __shfl_xor_sync(~0u, t, 8);
    t += __shfl_xor_sync(~0u, t, 4);
    t += __shfl_xor_sync(~0u, t, 2);
    t += __shfl_xor_sync(~0u, t, 1);
    float denom = t * 0.125f;

    osh[wIn][c4 * 4 + 0] = a0;   // same-value races within c4 class: benign
    osh[wIn][c4 * 4 + 1] = a1;
    osh[wIn][c4 * 4 + 2] = a2;
    osh[wIn][c4 * 4 + 3] = a3;
    __syncwarp();

    out[node * 32 + lane] = (e > s) ? (osh[wIn][lane] / denom) : 0.f;
}

// ---------------------------------------------------------------------------
// Launch: qkv on a side stream overlapping the edge pipeline.
// ---------------------------------------------------------------------------
extern "C" void kernel_launch(void* const* d_in, const int* in_sizes, int n_in,
                              void* d_out, int out_size)
{
    const float* X  = (const float*)d_in[0];
    const float* Wq = (const float*)d_in[1];
    const float* Wk = (const float*)d_in[2];
    const float* Wv = (const float*)d_in[3];
    const int*   ei = (const int*)d_in[4];
    float* out = (float*)d_out;

    const int N = in_sizes[0] / 256;   // 50000
    const int E = in_sizes[4] / 2;     // 1600000
    const int NB = (N + 1023) / 1024;
    const int E4 = (E + 3) / 4;

    static cudaStream_t s2 = nullptr;
    static cudaEvent_t evFork = nullptr, evQkv = nullptr;
    if (!s2) {
        cudaStreamCreateWithFlags(&s2, cudaStreamNonBlocking);
        cudaEventCreateWithFlags(&evFork, cudaEventDisableTiming);
        cudaEventCreateWithFlags(&evQkv, cudaEventDisableTiming);
    }

    cudaEventRecord(evFork, 0);
    cudaStreamWaitEvent(s2, evFork, 0);
    qkv_kernel<<<(N + QKV_TM - 1) / QKV_TM, 128, 0, s2>>>(X, Wq, Wk, Wv, N);
    cudaEventRecord(evQkv, s2);

    zero_cnt_kernel<<<(N + 255) / 256, 256>>>(N);
    hist_kernel<<<(E4 + 255) / 256, 256>>>(ei, E);
    scan_sum_kernel<<<NB, 1024>>>(N);
    scan_base_kernel<<<1, 64>>>(NB, N);
    scan_write_kernel<<<NB, 1024>>>(N);
    scatter_kernel<<<(E4 + 255) / 256, 256>>>(ei, E);

    cudaStreamWaitEvent(0, evQkv, 0);
    attn_kernel<<<(N + 7) / 8, 256>>>(out, N);
}

// round 7
// speedup vs baseline: 1.7590x; 1.7590x over previous
#include <cuda_runtime.h>
#include <cuda_bf16.h>

// Problem constants: N=50000 nodes, D=256, HS=32, E=1.6M edges
#define MAXN 50048
#define MAXE 1600000

__device__ float g_Q[MAXN * 32];
__device__ float g_K[MAXN * 32];
__device__ float g_V[MAXN * 32];
__device__ int   g_cnt[MAXN];
__device__ int   g_off[MAXN + 1];
__device__ int   g_cur[MAXN];
__device__ int   g_sorted[MAXE];
__device__ int   g_bsum[64];
__device__ int   g_bbase[64];

// ---------------------------------------------------------------------------
__global__ void zero_cnt_kernel(int n) {
    int i = blockIdx.x * blockDim.x + threadIdx.x;
    if (i < n) g_cnt[i] = 0;
}

// ---------------------------------------------------------------------------
// QKV projection: 128 thr, tile 128x96, packed f32x2 FMAs. (at fp32 floor)
// ---------------------------------------------------------------------------
#define QKV_TM 128

__global__ __launch_bounds__(128) void qkv_kernel(
    const float* __restrict__ X,
    const float* __restrict__ Wq,
    const float* __restrict__ Wk,
    const float* __restrict__ Wv,
    int nNodes)
{
    __shared__ float Xs[32][QKV_TM + 4];
    __shared__ float Ws[32][96];

    const int tid = threadIdx.x;
    const int tx  = tid & 15;
    const int ty  = tid >> 4;
    const int m0  = blockIdx.x * QKV_TM;

    unsigned long long accp[8][6];
    #pragma unroll
    for (int i = 0; i < 8; ++i)
        #pragma unroll
        for (int j = 0; j < 6; ++j) accp[i][j] = 0ull;

    for (int kc = 0; kc < 256; kc += 32) {
        #pragma unroll
        for (int it = 0; it < 8; ++it) {
            int idx = it * 128 + tid;
            int row = idx >> 3;
            int kq  = idx & 7;
            int gm  = m0 + row;
            float4 v = make_float4(0.f, 0.f, 0.f, 0.f);
            if (gm < nNodes)
                v = *reinterpret_cast<const float4*>(&X[gm * 256 + kc + kq * 4]);
            int kk = kq * 4;
            Xs[kk + 0][row] = v.x;
            Xs[kk + 1][row] = v.y;
            Xs[kk + 2][row] = v.z;
            Xs[kk + 3][row] = v.w;
        }
        #pragma unroll
        for (int idx = tid; idx < 32 * 96; idx += 128) {
            int k = idx / 96, j = idx - k * 96;
            const float* Wp = (j < 32) ? Wq : ((j < 64) ? Wk : Wv);
            Ws[k][j] = Wp[(kc + k) * 32 + (j & 31)];
        }
        __syncthreads();

        #pragma unroll
        for (int k = 0; k < 32; ++k) {
            float4 a0 = *reinterpret_cast<const float4*>(&Xs[k][tx * 4]);
            float4 a1 = *reinterpret_cast<const float4*>(&Xs[k][64 + tx * 4]);
            ulonglong2 b01 = *reinterpret_cast<const ulonglong2*>(&Ws[k][ty * 12]);
            ulonglong2 b23 = *reinterpret_cast<const ulonglong2*>(&Ws[k][ty * 12 + 4]);
            ulonglong2 b45 = *reinterpret_cast<const ulonglong2*>(&Ws[k][ty * 12 + 8]);
            unsigned long long bb[6] = {b01.x, b01.y, b23.x, b23.y, b45.x, b45.y};
            float av[8] = {a0.x, a0.y, a0.z, a0.w, a1.x, a1.y, a1.z, a1.w};
            #pragma unroll
            for (int i = 0; i < 8; ++i) {
                unsigned long long ad;
                asm("mov.b64 %0, {%1, %1};" : "=l"(ad) : "f"(av[i]));
                #pragma unroll
                for (int j = 0; j < 6; ++j)
                    asm("fma.rn.f32x2 %0, %1, %2, %0;"
                        : "+l"(accp[i][j]) : "l"(ad), "l"(bb[j]));
            }
        }
        __syncthreads();
    }

    const float qscale = 0.17677669529663687f;
    #pragma unroll
    for (int i = 0; i < 8; ++i) {
        int node = m0 + ((i < 4) ? (tx * 4 + i) : (64 + tx * 4 + i - 4));
        if (node >= nNodes) continue;
        #pragma unroll
        for (int j2 = 0; j2 < 6; ++j2) {
            float2 p = *reinterpret_cast<float2*>(&accp[i][j2]);
            int jj = ty * 12 + j2 * 2;
            float* dst = (jj < 32) ? g_Q : ((jj < 64) ? g_K : g_V);
            if (jj < 32) { p.x *= qscale; p.y *= qscale; }
            dst[node * 32 + (jj & 31)]     = p.x;
            dst[node * 32 + (jj & 31) + 1] = p.y;
        }
    }
}

// ---------------------------------------------------------------------------
__global__ void hist_kernel(const int* __restrict__ ei, int nEdges) {
    int i = blockIdx.x * blockDim.x + threadIdx.x;
    int e4 = i * 4;
    if (e4 + 3 < nEdges) {
        int4 r = *reinterpret_cast<const int4*>(&ei[e4]);
        atomicAdd(&g_cnt[r.x], 1);
        atomicAdd(&g_cnt[r.y], 1);
        atomicAdd(&g_cnt[r.z], 1);
        atomicAdd(&g_cnt[r.w], 1);
    } else {
        for (int e = e4; e < nEdges; ++e) atomicAdd(&g_cnt[ei[e]], 1);
    }
}

__global__ __launch_bounds__(1024) void scan_sum_kernel(int n) {
    int i = blockIdx.x * 1024 + threadIdx.x;
    int v = (i < n) ? g_cnt[i] : 0;
    #pragma unroll
    for (int o = 16; o; o >>= 1) v += __shfl_xor_sync(~0u, v, o);
    __shared__ int ws[32];
    if ((threadIdx.x & 31) == 0) ws[threadIdx.x >> 5] = v;
    __syncthreads();
    if (threadIdx.x < 32) {
        int s = ws[threadIdx.x];
        #pragma unroll
        for (int o = 16; o; o >>= 1) s += __shfl_xor_sync(~0u, s, o);
        if (threadIdx.x == 0) g_bsum[blockIdx.x] = s;
    }
}

__global__ void scan_base_kernel(int nb, int n) {
    __shared__ int sh[64];
    int t = threadIdx.x;
    int v = (t < nb) ? g_bsum[t] : 0;
    sh[t] = v;
    __syncthreads();
    #pragma unroll
    for (int o = 1; o < 64; o <<= 1) {
        int x = (t >= o) ? sh[t - o] : 0;
        __syncthreads();
        sh[t] += x;
        __syncthreads();
    }
    if (t < nb) g_bbase[t] = sh[t] - v;
    if (t == 63) g_off[n] = sh[63];
}

__global__ __launch_bounds__(1024) void scan_write_kernel(int n) {
    int i = blockIdx.x * 1024 + threadIdx.x;
    int lane = threadIdx.x & 31, w = threadIdx.x >> 5;
    int v = (i < n) ? g_cnt[i] : 0;
    int x = v;
    #pragma unroll
    for (int o = 1; o < 32; o <<= 1) {
        int y = __shfl_up_sync(~0u, x, o);
        if (lane >= o) x += y;
    }
    __shared__ int ws[32];
    if (lane == 31) ws[w] = x;
    __syncthreads();
    if (w == 0) {
        int s = ws[lane];
        #pragma unroll
        for (int o = 1; o < 32; o <<= 1) {
            int y = __shfl_up_sync(~0u, s, o);
            if (lane >= o) s += y;
        }
        ws[lane] = s;
    }
    __syncthreads();
    int base = g_bbase[blockIdx.x] + (w ? ws[w - 1] : 0);
    if (i < n) {
        int excl = base + x - v;
        g_off[i] = excl;
        g_cur[i] = excl;
    }
}

__global__ void scatter_kernel(const int* __restrict__ ei, int nEdges) {
    int i = blockIdx.x * blockDim.x + threadIdx.x;
    int e4 = i * 4;
    if (e4 + 3 < nEdges) {
        int4 r = *reinterpret_cast<const int4*>(&ei[e4]);
        int4 c = *reinterpret_cast<const int4*>(&ei[nEdges + e4]);
        g_sorted[atomicAdd(&g_cur[r.x], 1)] = c.x;
        g_sorted[atomicAdd(&g_cur[r.y], 1)] = c.y;
        g_sorted[atomicAdd(&g_cur[r.z], 1)] = c.z;
        g_sorted[atomicAdd(&g_cur[r.w], 1)] = c.w;
    } else {
        for (int e = e4; e < nEdges; ++e)
            g_sorted[atomicAdd(&g_cur[ei[e]], 1)] = ei[nEdges + e];
    }
}

// ---------------------------------------------------------------------------
// Attention. One warp per node; g=lane>>3 row-in-quad, c4=lane&7 col-group.
// Branch-free tile loop: tail lanes read node 0 (masked later by one SEL).
// K-phase and V-phase each run in 2 batches of 4 rows to keep regs < 64
// (launch_bounds(256,4) -> ~8 warps/SMSP for latency hiding).
// In-lane exp: after the c4-butterfly every lane of a row group holds the
// score, so the exp result IS the weight for that lane's V fragment.
// ---------------------------------------------------------------------------
__global__ __launch_bounds__(256, 4) void attn_kernel(float* __restrict__ out, int nNodes) {
    __shared__ float osh[8][32];

    const int wIn  = threadIdx.x >> 5;
    const int lane = threadIdx.x & 31;
    const int node = blockIdx.x * 8 + wIn;
    if (node >= nNodes) return;

    const int s = g_off[node];
    const int e = g_off[node + 1];

    const int c4 = lane & 7;
    const int g  = lane >> 3;

    float q = g_Q[node * 32 + lane];  // pre-scaled by 1/sqrt(32)
    float qc0 = __shfl_sync(~0u, q, c4 * 4 + 0);
    float qc1 = __shfl_sync(~0u, q, c4 * 4 + 1);
    float qc2 = __shfl_sync(~0u, q, c4 * 4 + 2);
    float qc3 = __shfl_sync(~0u, q, c4 * 4 + 3);

    float dsum = 0.f;                                // 8x over-counted denom
    unsigned long long accp0 = 0ull, accp1 = 0ull;   // cols c4*4..+3 partials

    for (int base = s; base < e; base += 32) {
        const int n = min(32, e - base);
        int cb = (base + lane < e) ? g_sorted[base + lane] : 0;

        int   cc[8];
        float ex[8];

        // ---- K phase: 2 batches of 4 rows (16 transient regs) ----
        #pragma unroll
        for (int b = 0; b < 2; ++b) {
            float4 kr[4];
            #pragma unroll
            for (int j = 0; j < 4; ++j) {
                int it = b * 4 + j;
                cc[it] = __shfl_sync(~0u, cb, it * 4 + g);
                kr[j] = *reinterpret_cast<const float4*>(&g_K[cc[it] * 32 + c4 * 4]);
            }
            #pragma unroll
            for (int j = 0; j < 4; ++j) {
                int it  = b * 4 + j;
                int row = it * 4 + g;
                float p = qc0 * kr[j].x;
                p = fmaf(qc1, kr[j].y, p);
                p = fmaf(qc2, kr[j].z, p);
                p = fmaf(qc3, kr[j].w, p);
                p += __shfl_xor_sync(~0u, p, 1);
                p += __shfl_xor_sync(~0u, p, 2);
                p += __shfl_xor_sync(~0u, p, 4);
                float exx = __expf(p);
                exx = (row < n) ? exx : 0.f;   // single SEL, no branch
                ex[it] = exx;
                dsum += exx;
            }
        }

        // ---- V phase: 2 batches of 4 rows ----
        #pragma unroll
        for (int b = 0; b < 2; ++b) {
            float4 vr[4];
            #pragma unroll
            for (int j = 0; j < 4; ++j)
                vr[j] = *reinterpret_cast<const float4*>(&g_V[cc[b * 4 + j] * 32 + c4 * 4]);
            #pragma unroll
            for (int j = 0; j < 4; ++j) {
                int it = b * 4 + j;
                unsigned long long wd;
                asm("mov.b64 %0, {%1, %1};" : "=l"(wd) : "f"(ex[it]));
                unsigned long long v01 = *reinterpret_cast<unsigned long long*>(&vr[j].x);
                unsigned long long v23 = *reinterpret_cast<unsigned long long*>(&vr[j].z);
                asm("fma.rn.f32x2 %0, %1, %2, %0;" : "+l"(accp0) : "l"(wd), "l"(v01));
                asm("fma.rn.f32x2 %0, %1, %2, %0;" : "+l"(accp1) : "l"(wd), "l"(v23));
            }
        }
    }

    // final reductions: columns over g bits; denom over all lanes (/8)
    float a0 = reinterpret_cast<float2*>(&accp0)->x;
    float a1 = reinterpret_cast<float2*>(&accp0)->y;
    float a2 = reinterpret_cast<float2*>(&accp1)->x;
    float a3 = reinterpret_cast<float2*>(&accp1)->y;
    #pragma unroll
    for (int m = 8; m <= 16; m <<= 1) {
        a0 += __shfl_xor_sync(~0u, a0, m);
        a1 += __shfl_xor_sync(~0u, a1, m);
        a2 += __shfl_xor_sync(~0u, a2, m);
        a3 += __shfl_xor_sync(~0u, a3, m);
    }
    float t = dsum;
    t += __shfl_xor_sync(~0u, t, 16);
    t += __shfl_xor_sync(~0u, t, 8);
    t += __shfl_xor_sync(~0u, t, 4);
    t += __shfl_xor_sync(~0u, t, 2);
    t += __shfl_xor_sync(~0u, t, 1);
    float denom = t * 0.125f;

    osh[wIn][c4 * 4 + 0] = a0;   // same-value races within c4 class: benign
    osh[wIn][c4 * 4 + 1] = a1;
    osh[wIn][c4 * 4 + 2] = a2;
    osh[wIn][c4 * 4 + 3] = a3;
    __syncwarp();

    out[node * 32 + lane] = (e > s) ? (osh[wIn][lane] / denom) : 0.f;
}

// ---------------------------------------------------------------------------
// Launch: qkv on a side stream overlapping the edge pipeline.
// ---------------------------------------------------------------------------
extern "C" void kernel_launch(void* const* d_in, const int* in_sizes, int n_in,
                              void* d_out, int out_size)
{
    const float* X  = (const float*)d_in[0];
    const float* Wq = (const float*)d_in[1];
    const float* Wk = (const float*)d_in[2];
    const float* Wv = (const float*)d_in[3];
    const int*   ei = (const int*)d_in[4];
    float* out = (float*)d_out;

    const int N = in_sizes[0] / 256;   // 50000
    const int E = in_sizes[4] / 2;     // 1600000
    const int NB = (N + 1023) / 1024;
    const int E4 = (E + 3) / 4;

    static cudaStream_t s2 = nullptr;
    static cudaEvent_t evFork = nullptr, evQkv = nullptr;
    if (!s2) {
        cudaStreamCreateWithFlags(&s2, cudaStreamNonBlocking);
        cudaEventCreateWithFlags(&evFork, cudaEventDisableTiming);
        cudaEventCreateWithFlags(&evQkv, cudaEventDisableTiming);
    }

    cudaEventRecord(evFork, 0);
    cudaStreamWaitEvent(s2, evFork, 0);
    qkv_kernel<<<(N + QKV_TM - 1) / QKV_TM, 128, 0, s2>>>(X, Wq, Wk, Wv, N);
    cudaEventRecord(evQkv, s2);

    zero_cnt_kernel<<<(N + 255) / 256, 256>>>(N);
    hist_kernel<<<(E4 + 255) / 256, 256>>>(ei, E);
    scan_sum_kernel<<<NB, 1024>>>(N);
    scan_base_kernel<<<1, 64>>>(NB, N);
    scan_write_kernel<<<NB, 1024>>>(N);
    scatter_kernel<<<(E4 + 255) / 256, 256>>>(ei, E);

    cudaStreamWaitEvent(0, evQkv, 0);
    attn_kernel<<<(N + 7) / 8, 256>>>(out, N);
}